// round 4
// baseline (speedup 1.0000x reference)
#include <cuda_runtime.h>
#include <math.h>
#include <stdint.h>

#define B 64
#define L 512
#define H 1024
#define NREL 3
#define KSPLIT 4
#define MAT (NREL * B * H)      // 196608 floats per [3][64][1024] matrix

// Scratch (device globals — no allocation allowed)
__device__ float g_part[KSPLIT * MAT];    // split-K GEMM partials (reused 3x)
__device__ float g_hrel[MAT];             // tanh(concat @ W_rel)
__device__ float g_target[MAT];           // h_rel @ Win
__device__ float g_wctx[MAT];             // weighted context

// Packed f32x2 helpers (FFMA2 — 2x fp32 FMA throughput, only reachable via PTX)
__device__ __forceinline__ void fma2(uint64_t& d, uint64_t a, uint64_t b) {
    asm("fma.rn.f32x2 %0, %1, %2, %0;" : "+l"(d) : "l"(a), "l"(b));
}
__device__ __forceinline__ uint64_t bcast2(float x) {
    uint64_t d;
    asm("mov.b64 %0, {%1, %1};" : "=l"(d) : "f"(x));
    return d;
}
__device__ __forceinline__ float2 unpack2(uint64_t v) {
    float2 r;
    asm("mov.b64 {%0, %1}, %2;" : "=f"(r.x), "=f"(r.y) : "l"(v));
    return r;
}

// ---------------------------------------------------------------------------
// Split-K GEMM over A = concat(A1[64,1024], A2[64,1024]) (row-major, stride
// 1024), W row-major [(K1+K2), 1024]. Plain (non-atomic) partials:
// Cpart[split][rel][64][1024]. BM=64, BN=64, BK=16. Inner loop uses packed
// f32x2 FMAs: A-side m-pairs load pre-packed straight from smem (As is [k][m]).
// grid = (16 n-tiles, KSPLIT, 3 rels), block = 256.
// ---------------------------------------------------------------------------
__global__ __launch_bounds__(256) void gemm_concat_kernel(
    const float* __restrict__ A1_0, const float* __restrict__ A1_1, const float* __restrict__ A1_2,
    const float* __restrict__ A2_0, const float* __restrict__ A2_1, const float* __restrict__ A2_2,
    const float* __restrict__ W0,  const float* __restrict__ W1,  const float* __restrict__ W2,
    float* __restrict__ Cpart, int K1len, int kchunk)
{
    const int rel = blockIdx.z;
    const float* A1 = (rel == 0) ? A1_0 : (rel == 1) ? A1_1 : A1_2;
    const float* A2 = (rel == 0) ? A2_0 : (rel == 1) ? A2_1 : A2_2;
    const float* W  = (rel == 0) ? W0  : (rel == 1) ? W1  : W2;
    float* C = Cpart + (size_t)blockIdx.y * MAT + (size_t)rel * (B * H);

    const int n0   = blockIdx.x * 64;
    const int kbeg = blockIdx.y * kchunk;
    const int kend = kbeg + kchunk;

    __shared__ __align__(16) float As[16][64];
    __shared__ __align__(16) float Ws[16][64];

    const int tid = threadIdx.x;
    const int a_m = tid >> 2;            // 0..63
    const int a_k = (tid & 3) * 4;       // 0,4,8,12
    const int w_k = tid >> 4;            // 0..15
    const int w_n = (tid & 15) * 4;      // 0..60
    const int tx  = tid & 15;
    const int ty  = tid >> 4;

    // acc2[mp][n] : mp = m-pair (m = ty*4 + mp*2 + {0,1}), n = 0..3
    uint64_t acc2[2][4] = {};

    for (int k0 = kbeg; k0 < kend; k0 += 16) {
        // BK=16 tiles never straddle the concat boundary (K1len multiple of 16)
        const float* Aptr = (k0 < K1len)
            ? (A1 + (size_t)a_m * H + (k0 + a_k))
            : (A2 + (size_t)a_m * H + (k0 - K1len + a_k));
        float4 av = *(const float4*)Aptr;
        float4 wv = *(const float4*)(W + (size_t)(k0 + w_k) * H + n0 + w_n);
        __syncthreads();
        As[a_k + 0][a_m] = av.x;
        As[a_k + 1][a_m] = av.y;
        As[a_k + 2][a_m] = av.z;
        As[a_k + 3][a_m] = av.w;
        *(float4*)&Ws[w_k][w_n] = wv;
        __syncthreads();
        #pragma unroll
        for (int k = 0; k < 16; k++) {
            ulonglong2 a = *(const ulonglong2*)&As[k][ty * 4];   // (m0,m1),(m2,m3)
            float4 b = *(const float4*)&Ws[k][tx * 4];
            uint64_t b0 = bcast2(b.x), b1 = bcast2(b.y), b2 = bcast2(b.z), b3 = bcast2(b.w);
            fma2(acc2[0][0], a.x, b0); fma2(acc2[0][1], a.x, b1);
            fma2(acc2[0][2], a.x, b2); fma2(acc2[0][3], a.x, b3);
            fma2(acc2[1][0], a.y, b0); fma2(acc2[1][1], a.y, b1);
            fma2(acc2[1][2], a.y, b2); fma2(acc2[1][3], a.y, b3);
        }
    }
    #pragma unroll
    for (int mp = 0; mp < 2; mp++) {
        float2 c0 = unpack2(acc2[mp][0]);
        float2 c1 = unpack2(acc2[mp][1]);
        float2 c2 = unpack2(acc2[mp][2]);
        float2 c3 = unpack2(acc2[mp][3]);
        int m = ty * 4 + mp * 2;
        *(float4*)(C + (size_t)(m + 0) * H + n0 + tx * 4) = make_float4(c0.x, c1.x, c2.x, c3.x);
        *(float4*)(C + (size_t)(m + 1) * H + n0 + tx * 4) = make_float4(c0.y, c1.y, c2.y, c3.y);
    }
}

// Deterministic split-K reduction (+ optional tanh), float4-vectorized.
__global__ void reduce4_kernel(const float* __restrict__ in, float* __restrict__ outp, int do_tanh)
{
    int i = blockIdx.x * 256 + threadIdx.x;        // float4 index, 0..49151
    const int S = MAT / 4;
    if (i >= S) return;
    const float4* p = (const float4*)in;
    float4 a = p[i], b = p[i + S], c = p[i + 2 * S], d = p[i + 3 * S];
    float4 v;
    v.x = a.x + b.x + c.x + d.x;
    v.y = a.y + b.y + c.y + d.y;
    v.z = a.z + b.z + c.z + d.z;
    v.w = a.w + b.w + c.w + d.w;
    if (do_tanh) { v.x = tanhf(v.x); v.y = tanhf(v.y); v.z = tanhf(v.z); v.w = tanhf(v.w); }
    ((float4*)outp)[i] = v;
}

// ---------------------------------------------------------------------------
// Fused attention: scores -> softmax -> weighted context, one block per batch
// element, all intermediates in smem. grid = 64, block = 1024.
//   Phase A: scores[rel][l] = dot(enc[b,l,:], target[rel][b,:])  (enc from DRAM)
//   Phase B: softmax over L (3 warps, one per rel)
//   Phase C: wctx[rel][b][h] = sum_l p[rel][l] * enc[b][l][h]    (enc from L2)
// ---------------------------------------------------------------------------
__global__ __launch_bounds__(1024) void fused_attn_kernel(
    const float* __restrict__ enc, const float* __restrict__ target, float* __restrict__ wctx)
{
    const int b    = blockIdx.x;
    const int tid  = threadIdx.x;
    const int warp = tid >> 5;
    const int lane = tid & 31;

    __shared__ __align__(16) float st[3][H];          // 12 KB targets
    __shared__ __align__(16) float sc[3][L];          // 6 KB  scores/probs
    __shared__ __align__(16) float4 spart[4][3][256]; // 48 KB wctx l-partials

    // Phase A: stage targets, compute scores (one warp per l-row, 16 rows/warp)
    for (int i = tid; i < 3 * H; i += 1024)
        st[i >> 10][i & 1023] = target[(size_t)((i >> 10) * B + b) * H + (i & 1023)];
    __syncthreads();

    for (int li = 0; li < 16; li++) {
        const int l = li * 32 + warp;
        const float4* erow = (const float4*)(enc + ((size_t)b * L + l) * H);
        float s0 = 0.f, s1 = 0.f, s2 = 0.f;
        #pragma unroll
        for (int i = 0; i < 8; i++) {
            int h4 = lane + i * 32;
            float4 e  = erow[h4];
            float4 t0 = *(const float4*)&st[0][h4 * 4];
            float4 t1 = *(const float4*)&st[1][h4 * 4];
            float4 t2 = *(const float4*)&st[2][h4 * 4];
            s0 += e.x * t0.x + e.y * t0.y + e.z * t0.z + e.w * t0.w;
            s1 += e.x * t1.x + e.y * t1.y + e.z * t1.z + e.w * t1.w;
            s2 += e.x * t2.x + e.y * t2.y + e.z * t2.z + e.w * t2.w;
        }
        #pragma unroll
        for (int o = 16; o > 0; o >>= 1) {
            s0 += __shfl_down_sync(0xffffffffu, s0, o);
            s1 += __shfl_down_sync(0xffffffffu, s1, o);
            s2 += __shfl_down_sync(0xffffffffu, s2, o);
        }
        if (lane == 0) { sc[0][l] = s0; sc[1][l] = s1; sc[2][l] = s2; }
    }
    __syncthreads();

    // Phase B: softmax over L=512 per rel (warps 0..2)
    if (warp < 3) {
        float* p = sc[warp];
        float v[16];
        float mx = -1e30f;
        #pragma unroll
        for (int i = 0; i < 16; i++) { v[i] = p[lane + i * 32]; mx = fmaxf(mx, v[i]); }
        #pragma unroll
        for (int o = 16; o > 0; o >>= 1) mx = fmaxf(mx, __shfl_xor_sync(0xffffffffu, mx, o));
        float sum = 0.f;
        #pragma unroll
        for (int i = 0; i < 16; i++) { v[i] = __expf(v[i] - mx); sum += v[i]; }
        #pragma unroll
        for (int o = 16; o > 0; o >>= 1) sum += __shfl_xor_sync(0xffffffffu, sum, o);
        float inv = 1.f / sum;
        #pragma unroll
        for (int i = 0; i < 16; i++) p[lane + i * 32] = v[i] * inv;
    }
    __syncthreads();

    // Phase C: weighted context. thread = (ls, hcol): ls = l-split (4x128), hcol float4
    {
        const int hcol = tid & 255;
        const int ls   = tid >> 8;
        const float4* e = (const float4*)(enc + ((size_t)b * L + ls * 128) * H) + hcol;
        float4 a0 = {0,0,0,0}, a1 = {0,0,0,0}, a2 = {0,0,0,0};
        #pragma unroll 8
        for (int l = 0; l < 128; l++) {
            float4 ev = e[(size_t)l * 256];
            float p0 = sc[0][ls * 128 + l], p1 = sc[1][ls * 128 + l], p2 = sc[2][ls * 128 + l];
            a0.x += p0 * ev.x; a0.y += p0 * ev.y; a0.z += p0 * ev.z; a0.w += p0 * ev.w;
            a1.x += p1 * ev.x; a1.y += p1 * ev.y; a1.z += p1 * ev.z; a1.w += p1 * ev.w;
            a2.x += p2 * ev.x; a2.y += p2 * ev.y; a2.z += p2 * ev.z; a2.w += p2 * ev.w;
        }
        spart[ls][0][hcol] = a0;
        spart[ls][1][hcol] = a1;
        spart[ls][2][hcol] = a2;
    }
    __syncthreads();

    // Reduce 4 l-splits, write wctx[rel][b][:]
    if (tid < 768) {
        const int rel = tid >> 8, hcol = tid & 255;
        float4 a = spart[0][rel][hcol], c = spart[1][rel][hcol];
        float4 d = spart[2][rel][hcol], f = spart[3][rel][hcol];
        float4 v;
        v.x = (a.x + c.x) + (d.x + f.x);
        v.y = (a.y + c.y) + (d.y + f.y);
        v.z = (a.z + c.z) + (d.z + f.z);
        v.w = (a.w + c.w) + (d.w + f.w);
        ((float4*)wctx)[(size_t)(rel * B + b) * 256 + hcol] = v;
    }
}

// Sum final-GEMM split-K partials, tanh, broadcast F times to out[rel][b][f][h].
__global__ void bcast_kernel(const float* __restrict__ part, float* __restrict__ out, int F)
{
    int idx = blockIdx.x * 256 + threadIdx.x;      // 0..49151 float4 units
    const float4* p = (const float4*)part;
    const int S = MAT / 4;                         // 49152
    float4 v0 = p[idx], v1 = p[idx + S], v2 = p[idx + 2 * S], v3 = p[idx + 3 * S];
    float4 v;
    v.x = tanhf(v0.x + v1.x + v2.x + v3.x);
    v.y = tanhf(v0.y + v1.y + v2.y + v3.y);
    v.z = tanhf(v0.z + v1.z + v2.z + v3.z);
    v.w = tanhf(v0.w + v1.w + v2.w + v3.w);
    int rb = idx >> 8;                             // rel*64 + b
    int h4 = idx & 255;
    float4* o = (float4*)out + (size_t)rb * F * 256 + h4;
    for (int f = 0; f < F; f++) o[(size_t)f * 256] = v;
}

// ---------------------------------------------------------------------------
extern "C" void kernel_launch(void* const* d_in, const int* in_sizes, int n_in,
                              void* d_out, int out_size)
{
    const float* h_s     = (const float*)d_in[0];
    const float* h_o     = (const float*)d_in[1];
    const float* h_a     = (const float*)d_in[2];
    const float* enc     = (const float*)d_in[3];
    // d_in[4] = full_feature_len (derived from out_size instead)
    const float* W_as    = (const float*)d_in[5];
    const float* W_so    = (const float*)d_in[6];
    const float* W_oa    = (const float*)d_in[7];
    const float* Win_as  = (const float*)d_in[8];
    const float* Win_so  = (const float*)d_in[9];
    const float* Win_oa  = (const float*)d_in[10];
    const float* Wout_as = (const float*)d_in[11];
    const float* Wout_so = (const float*)d_in[12];
    const float* Wout_oa = (const float*)d_in[13];
    float* out = (float*)d_out;
    const int F = out_size / (NREL * B * H);       // 36

    float *p_part, *p_hrel, *p_target, *p_wctx;
    cudaGetSymbolAddress((void**)&p_part,   g_part);
    cudaGetSymbolAddress((void**)&p_hrel,   g_hrel);
    cudaGetSymbolAddress((void**)&p_target, g_target);
    cudaGetSymbolAddress((void**)&p_wctx,   g_wctx);

    const dim3 gg(16, KSPLIT, 3);

    // 1) h_rel = tanh(concat(h1,h2) @ W_rel)   [as: (a,s), so: (s,o), oa: (o,a)]
    gemm_concat_kernel<<<gg, 256>>>(h_a, h_s, h_o,   h_s, h_o, h_a,
                                    W_as, W_so, W_oa, p_part, H, 512);
    reduce4_kernel<<<192, 256>>>(p_part, p_hrel, 1);

    // 2) target = h_rel @ Win_rel
    gemm_concat_kernel<<<gg, 256>>>(p_hrel, p_hrel + B * H, p_hrel + 2 * B * H,
                                    p_hrel, p_hrel, p_hrel,   // unused (K2 side never hit)
                                    Win_as, Win_so, Win_oa, p_part, H, 256);
    reduce4_kernel<<<192, 256>>>(p_part, p_target, 0);

    // 3) fused scores -> softmax -> weighted context
    fused_attn_kernel<<<64, 1024>>>(enc, p_target, p_wctx);

    // 4) h_final = tanh(concat(wctx, h_rel) @ Wout_rel), broadcast to out
    gemm_concat_kernel<<<gg, 256>>>(p_wctx, p_wctx + B * H, p_wctx + 2 * B * H,
                                    p_hrel, p_hrel + B * H, p_hrel + 2 * B * H,
                                    Wout_as, Wout_so, Wout_oa, p_part, H, 512);
    bcast_kernel<<<192, 256>>>(p_part, out, F);
}

// round 5
// speedup vs baseline: 1.0406x; 1.0406x over previous
#include <cuda_runtime.h>
#include <math.h>
#include <stdint.h>

#define B 64
#define L 512
#define H 1024
#define NREL 3
#define KSPLIT 4
#define MAT (NREL * B * H)      // 196608 floats per [3][64][1024] matrix

// Scratch (device globals — no allocation allowed)
__device__ float g_part[KSPLIT * MAT];    // split-K GEMM partials (reused 3x)
__device__ float g_hrel[MAT];             // tanh(concat @ W_rel)
__device__ float g_target[MAT];           // h_rel @ Win
__device__ float g_scores[NREL * B * L];  // scores -> probs (in place)
__device__ float g_wpart[KSPLIT * MAT];   // weighted-ctx L-split partials
__device__ float g_wctx[MAT];             // weighted context

// Packed f32x2 helpers (FFMA2 — 2x fp32 FMA throughput, only reachable via PTX)
__device__ __forceinline__ void fma2(uint64_t& d, uint64_t a, uint64_t b) {
    asm("fma.rn.f32x2 %0, %1, %2, %0;" : "+l"(d) : "l"(a), "l"(b));
}
__device__ __forceinline__ uint64_t bcast2(float x) {
    uint64_t d;
    asm("mov.b64 %0, {%1, %1};" : "=l"(d) : "f"(x));
    return d;
}
__device__ __forceinline__ float2 unpack2(uint64_t v) {
    float2 r;
    asm("mov.b64 {%0, %1}, %2;" : "=f"(r.x), "=f"(r.y) : "l"(v));
    return r;
}

// ---------------------------------------------------------------------------
// Split-K GEMM over A = concat(A1[64,1024], A2[64,1024]) (row-major, stride
// 1024), W row-major [(K1+K2), 1024]. Plain (non-atomic) partials:
// Cpart[split][rel][64][1024]. BM=64, BN=64, BK=16. Inner loop uses packed
// f32x2 FMAs: A-side m-pairs load pre-packed straight from smem (As is [k][m]).
// grid = (16 n-tiles, KSPLIT, 3 rels), block = 256.
// ---------------------------------------------------------------------------
__global__ __launch_bounds__(256) void gemm_concat_kernel(
    const float* __restrict__ A1_0, const float* __restrict__ A1_1, const float* __restrict__ A1_2,
    const float* __restrict__ A2_0, const float* __restrict__ A2_1, const float* __restrict__ A2_2,
    const float* __restrict__ W0,  const float* __restrict__ W1,  const float* __restrict__ W2,
    float* __restrict__ Cpart, int K1len, int kchunk)
{
    const int rel = blockIdx.z;
    const float* A1 = (rel == 0) ? A1_0 : (rel == 1) ? A1_1 : A1_2;
    const float* A2 = (rel == 0) ? A2_0 : (rel == 1) ? A2_1 : A2_2;
    const float* W  = (rel == 0) ? W0  : (rel == 1) ? W1  : W2;
    float* C = Cpart + (size_t)blockIdx.y * MAT + (size_t)rel * (B * H);

    const int n0   = blockIdx.x * 64;
    const int kbeg = blockIdx.y * kchunk;
    const int kend = kbeg + kchunk;

    __shared__ __align__(16) float As[16][64];
    __shared__ __align__(16) float Ws[16][64];

    const int tid = threadIdx.x;
    const int a_m = tid >> 2;            // 0..63
    const int a_k = (tid & 3) * 4;       // 0,4,8,12
    const int w_k = tid >> 4;            // 0..15
    const int w_n = (tid & 15) * 4;      // 0..60
    const int tx  = tid & 15;
    const int ty  = tid >> 4;

    // acc2[mp][n] : mp = m-pair (m = ty*4 + mp*2 + {0,1}), n = 0..3
    uint64_t acc2[2][4] = {};

    for (int k0 = kbeg; k0 < kend; k0 += 16) {
        // BK=16 tiles never straddle the concat boundary (K1len multiple of 16)
        const float* Aptr = (k0 < K1len)
            ? (A1 + (size_t)a_m * H + (k0 + a_k))
            : (A2 + (size_t)a_m * H + (k0 - K1len + a_k));
        float4 av = *(const float4*)Aptr;
        float4 wv = *(const float4*)(W + (size_t)(k0 + w_k) * H + n0 + w_n);
        __syncthreads();
        As[a_k + 0][a_m] = av.x;
        As[a_k + 1][a_m] = av.y;
        As[a_k + 2][a_m] = av.z;
        As[a_k + 3][a_m] = av.w;
        *(float4*)&Ws[w_k][w_n] = wv;
        __syncthreads();
        #pragma unroll
        for (int k = 0; k < 16; k++) {
            ulonglong2 a = *(const ulonglong2*)&As[k][ty * 4];   // (m0,m1),(m2,m3)
            float4 b = *(const float4*)&Ws[k][tx * 4];
            uint64_t b0 = bcast2(b.x), b1 = bcast2(b.y), b2 = bcast2(b.z), b3 = bcast2(b.w);
            fma2(acc2[0][0], a.x, b0); fma2(acc2[0][1], a.x, b1);
            fma2(acc2[0][2], a.x, b2); fma2(acc2[0][3], a.x, b3);
            fma2(acc2[1][0], a.y, b0); fma2(acc2[1][1], a.y, b1);
            fma2(acc2[1][2], a.y, b2); fma2(acc2[1][3], a.y, b3);
        }
    }
    #pragma unroll
    for (int mp = 0; mp < 2; mp++) {
        float2 c0 = unpack2(acc2[mp][0]);
        float2 c1 = unpack2(acc2[mp][1]);
        float2 c2 = unpack2(acc2[mp][2]);
        float2 c3 = unpack2(acc2[mp][3]);
        int m = ty * 4 + mp * 2;
        *(float4*)(C + (size_t)(m + 0) * H + n0 + tx * 4) = make_float4(c0.x, c1.x, c2.x, c3.x);
        *(float4*)(C + (size_t)(m + 1) * H + n0 + tx * 4) = make_float4(c0.y, c1.y, c2.y, c3.y);
    }
}

// Deterministic split-K reduction (+ optional tanh), float4-vectorized.
__global__ void reduce4_kernel(const float* __restrict__ in, float* __restrict__ outp, int do_tanh)
{
    int i = blockIdx.x * 256 + threadIdx.x;        // float4 index, 0..49151
    const int S = MAT / 4;
    if (i >= S) return;
    const float4* p = (const float4*)in;
    float4 a = p[i], b = p[i + S], c = p[i + 2 * S], d = p[i + 3 * S];
    float4 v;
    v.x = a.x + b.x + c.x + d.x;
    v.y = a.y + b.y + c.y + d.y;
    v.z = a.z + b.z + c.z + d.z;
    v.w = a.w + b.w + c.w + d.w;
    if (do_tanh) { v.x = tanhf(v.x); v.y = tanhf(v.y); v.z = tanhf(v.z); v.w = tanhf(v.w); }
    ((float4*)outp)[i] = v;
}

// scores[rel][b][l] = dot(enc[b,l,:], target[rel][b,:]).  One warp per l-row,
// 8 rows per block. Targets cached in smem (12 KB). grid = (64 l-chunks, 64 b).
__global__ __launch_bounds__(256) void scores_kernel(
    const float* __restrict__ enc, const float* __restrict__ target, float* __restrict__ scores)
{
    const int b    = blockIdx.y;
    const int warp = threadIdx.x >> 5;
    const int lane = threadIdx.x & 31;
    const int l    = blockIdx.x * 8 + warp;

    __shared__ __align__(16) float st[3][H];
    for (int i = threadIdx.x; i < 3 * H; i += 256)
        st[i >> 10][i & 1023] = target[(size_t)((i >> 10) * B + b) * H + (i & 1023)];
    __syncthreads();

    const float4* erow = (const float4*)(enc + ((size_t)b * L + l) * H);
    float s0 = 0.f, s1 = 0.f, s2 = 0.f;
    #pragma unroll
    for (int i = 0; i < 8; i++) {
        int h4 = lane + i * 32;
        float4 e  = erow[h4];
        float4 t0 = *(const float4*)&st[0][h4 * 4];
        float4 t1 = *(const float4*)&st[1][h4 * 4];
        float4 t2 = *(const float4*)&st[2][h4 * 4];
        s0 += e.x * t0.x + e.y * t0.y + e.z * t0.z + e.w * t0.w;
        s1 += e.x * t1.x + e.y * t1.y + e.z * t1.z + e.w * t1.w;
        s2 += e.x * t2.x + e.y * t2.y + e.z * t2.z + e.w * t2.w;
    }
    #pragma unroll
    for (int o = 16; o > 0; o >>= 1) {
        s0 += __shfl_down_sync(0xffffffffu, s0, o);
        s1 += __shfl_down_sync(0xffffffffu, s1, o);
        s2 += __shfl_down_sync(0xffffffffu, s2, o);
    }
    if (lane == 0) {
        scores[(size_t)(0 * B + b) * L + l] = s0;
        scores[(size_t)(1 * B + b) * L + l] = s1;
        scores[(size_t)(2 * B + b) * L + l] = s2;
    }
}

// In-place softmax over L=512 for 192 rows, one warp per row (16 elems/lane).
__global__ void softmax_kernel(float* __restrict__ s)
{
    int row  = blockIdx.x * 8 + (threadIdx.x >> 5);
    int lane = threadIdx.x & 31;
    float* p = s + (size_t)row * L;
    float v[16];
    float mx = -1e30f;
    #pragma unroll
    for (int i = 0; i < 16; i++) { v[i] = p[lane + i * 32]; mx = fmaxf(mx, v[i]); }
    #pragma unroll
    for (int o = 16; o > 0; o >>= 1) mx = fmaxf(mx, __shfl_xor_sync(0xffffffffu, mx, o));
    float sum = 0.f;
    #pragma unroll
    for (int i = 0; i < 16; i++) { v[i] = __expf(v[i] - mx); sum += v[i]; }
    #pragma unroll
    for (int o = 16; o > 0; o >>= 1) sum += __shfl_xor_sync(0xffffffffu, sum, o);
    float inv = 1.f / sum;
    #pragma unroll
    for (int i = 0; i < 16; i++) p[lane + i * 32] = v[i] * inv;
}

// wpart[ls][rel][b][h] = sum over 128 l's of p[rel][b][l] * enc[b][l][h].
// grid = (4 l-splits, 64 b), block 256 (one float4 h-column per thread).
__global__ __launch_bounds__(256) void wctx_kernel(
    const float* __restrict__ enc, const float* __restrict__ probs, float* __restrict__ wpart)
{
    const int ls = blockIdx.x;
    const int b  = blockIdx.y;
    const int t  = threadIdx.x;

    __shared__ float sp[3][128];
    for (int i = t; i < 3 * 128; i += 256)
        sp[i >> 7][i & 127] = probs[(size_t)((i >> 7) * B + b) * L + ls * 128 + (i & 127)];
    __syncthreads();

    const float4* e = (const float4*)(enc + ((size_t)b * L + ls * 128) * H) + t;
    float4 a0 = {0,0,0,0}, a1 = {0,0,0,0}, a2 = {0,0,0,0};
    #pragma unroll 4
    for (int l = 0; l < 128; l++) {
        float4 ev = e[(size_t)l * 256];
        float p0 = sp[0][l], p1 = sp[1][l], p2 = sp[2][l];
        a0.x += p0 * ev.x; a0.y += p0 * ev.y; a0.z += p0 * ev.z; a0.w += p0 * ev.w;
        a1.x += p1 * ev.x; a1.y += p1 * ev.y; a1.z += p1 * ev.z; a1.w += p1 * ev.w;
        a2.x += p2 * ev.x; a2.y += p2 * ev.y; a2.z += p2 * ev.z; a2.w += p2 * ev.w;
    }
    float4* w = (float4*)(wpart + (size_t)ls * MAT);
    w[(size_t)(0 * B + b) * 256 + t] = a0;
    w[(size_t)(1 * B + b) * 256 + t] = a1;
    w[(size_t)(2 * B + b) * 256 + t] = a2;
}

// Sum final-GEMM split-K partials, tanh, broadcast F times to out[rel][b][f][h].
__global__ void bcast_kernel(const float* __restrict__ part, float* __restrict__ out, int F)
{
    int idx = blockIdx.x * 256 + threadIdx.x;      // 0..49151 float4 units
    const float4* p = (const float4*)part;
    const int S = MAT / 4;                         // 49152
    float4 v0 = p[idx], v1 = p[idx + S], v2 = p[idx + 2 * S], v3 = p[idx + 3 * S];
    float4 v;
    v.x = tanhf(v0.x + v1.x + v2.x + v3.x);
    v.y = tanhf(v0.y + v1.y + v2.y + v3.y);
    v.z = tanhf(v0.z + v1.z + v2.z + v3.z);
    v.w = tanhf(v0.w + v1.w + v2.w + v3.w);
    int rb = idx >> 8;                             // rel*64 + b
    int h4 = idx & 255;
    float4* o = (float4*)out + (size_t)rb * F * 256 + h4;
    for (int f = 0; f < F; f++) o[(size_t)f * 256] = v;
}

// ---------------------------------------------------------------------------
extern "C" void kernel_launch(void* const* d_in, const int* in_sizes, int n_in,
                              void* d_out, int out_size)
{
    const float* h_s     = (const float*)d_in[0];
    const float* h_o     = (const float*)d_in[1];
    const float* h_a     = (const float*)d_in[2];
    const float* enc     = (const float*)d_in[3];
    // d_in[4] = full_feature_len (derived from out_size instead)
    const float* W_as    = (const float*)d_in[5];
    const float* W_so    = (const float*)d_in[6];
    const float* W_oa    = (const float*)d_in[7];
    const float* Win_as  = (const float*)d_in[8];
    const float* Win_so  = (const float*)d_in[9];
    const float* Win_oa  = (const float*)d_in[10];
    const float* Wout_as = (const float*)d_in[11];
    const float* Wout_so = (const float*)d_in[12];
    const float* Wout_oa = (const float*)d_in[13];
    float* out = (float*)d_out;
    const int F = out_size / (NREL * B * H);       // 36

    float *p_part, *p_hrel, *p_target, *p_scores, *p_wpart, *p_wctx;
    cudaGetSymbolAddress((void**)&p_part,   g_part);
    cudaGetSymbolAddress((void**)&p_hrel,   g_hrel);
    cudaGetSymbolAddress((void**)&p_target, g_target);
    cudaGetSymbolAddress((void**)&p_scores, g_scores);
    cudaGetSymbolAddress((void**)&p_wpart,  g_wpart);
    cudaGetSymbolAddress((void**)&p_wctx,   g_wctx);

    const dim3 gg(16, KSPLIT, 3);

    // 1) h_rel = tanh(concat(h1,h2) @ W_rel)   [as: (a,s), so: (s,o), oa: (o,a)]
    gemm_concat_kernel<<<gg, 256>>>(h_a, h_s, h_o,   h_s, h_o, h_a,
                                    W_as, W_so, W_oa, p_part, H, 512);
    reduce4_kernel<<<192, 256>>>(p_part, p_hrel, 1);

    // 2) target = h_rel @ Win_rel
    gemm_concat_kernel<<<gg, 256>>>(p_hrel, p_hrel + B * H, p_hrel + 2 * B * H,
                                    p_hrel, p_hrel, p_hrel,   // unused (K2 side never hit)
                                    Win_as, Win_so, Win_oa, p_part, H, 256);
    reduce4_kernel<<<192, 256>>>(p_part, p_target, 0);

    // 3) scores = enc . target ; softmax ; weighted ctx  (split, full-grid)
    scores_kernel<<<dim3(64, 64), 256>>>(enc, p_target, p_scores);
    softmax_kernel<<<24, 256>>>(p_scores);
    wctx_kernel<<<dim3(4, 64), 256>>>(enc, p_scores, p_wpart);
    reduce4_kernel<<<192, 256>>>(p_wpart, p_wctx, 0);

    // 4) h_final = tanh(concat(wctx, h_rel) @ Wout_rel), broadcast to out
    gemm_concat_kernel<<<gg, 256>>>(p_wctx, p_wctx + B * H, p_wctx + 2 * B * H,
                                    p_hrel, p_hrel + B * H, p_hrel + 2 * B * H,
                                    Wout_as, Wout_so, Wout_oa, p_part, H, 512);
    bcast_kernel<<<192, 256>>>(p_part, out, F);
}

// round 6
// speedup vs baseline: 1.0982x; 1.0553x over previous
#include <cuda_runtime.h>
#include <math.h>

#define B 64
#define L 512
#define H 1024
#define NREL 3
#define KSPLIT 8
#define MAT (NREL * B * H)      // 196608 floats per [3][64][1024] matrix

// Scratch (device globals — no allocation allowed)
__device__ float g_part[KSPLIT * MAT];    // split-K GEMM partials (reused 3x)
__device__ float g_hrel[MAT];             // tanh(concat @ W_rel)
__device__ float g_target[MAT];           // h_rel @ Win
__device__ float g_scores[NREL * B * L];  // raw scores
__device__ float g_wpart[4 * MAT];        // weighted-ctx L-split partials
__device__ float g_wctx[MAT];             // weighted context

// ---------------------------------------------------------------------------
// Split-K GEMM over A = concat(A1[64,1024], A2[64,1024]) (row-major, stride
// 1024), W row-major [(K1+K2), 1024]. Plain (non-atomic) partials:
// Cpart[split][rel][64][1024]. BM=64, BN=128, BK=16, thread tile 4m x 8n.
// Next k-tile's gmem loads are prefetched before the compute phase.
// grid = (8 n-tiles, KSPLIT, 3 rels), block = 256.
// ---------------------------------------------------------------------------
__global__ __launch_bounds__(256) void gemm_concat_kernel(
    const float* __restrict__ A1_0, const float* __restrict__ A1_1, const float* __restrict__ A1_2,
    const float* __restrict__ A2_0, const float* __restrict__ A2_1, const float* __restrict__ A2_2,
    const float* __restrict__ W0,  const float* __restrict__ W1,  const float* __restrict__ W2,
    float* __restrict__ Cpart, int K1len, int kchunk)
{
    const int rel = blockIdx.z;
    const float* A1 = (rel == 0) ? A1_0 : (rel == 1) ? A1_1 : A1_2;
    const float* A2 = (rel == 0) ? A2_0 : (rel == 1) ? A2_1 : A2_2;
    const float* W  = (rel == 0) ? W0  : (rel == 1) ? W1  : W2;
    float* C = Cpart + (size_t)blockIdx.y * MAT + (size_t)rel * (B * H);

    const int n0   = blockIdx.x * 128;
    const int kbeg = blockIdx.y * kchunk;
    const int ntiles = kchunk / 16;

    __shared__ __align__(16) float As[16][64];     // 4 KB
    __shared__ __align__(16) float Ws[16][128];    // 8 KB

    const int tid = threadIdx.x;
    const int a_m = tid >> 2;            // 0..63
    const int a_k = (tid & 3) * 4;       // 0,4,8,12
    const int w_k = tid >> 4;            // 0..15
    const int w_n = (tid & 15) * 8;      // 0..120
    const int tx  = tid & 15;            // n-group (8 cols)
    const int ty  = tid >> 4;            // m-group (4 rows)

    float acc[4][8] = {};

    // Prologue: load tile 0
    int k0 = kbeg;
    const float* Aptr = (k0 < K1len)
        ? (A1 + (size_t)a_m * H + (k0 + a_k))
        : (A2 + (size_t)a_m * H + (k0 - K1len + a_k));
    float4 av  = *(const float4*)Aptr;
    float4 wv0 = *(const float4*)(W + (size_t)(k0 + w_k) * H + n0 + w_n);
    float4 wv1 = *(const float4*)(W + (size_t)(k0 + w_k) * H + n0 + w_n + 4);

    for (int t = 0; t < ntiles; t++) {
        __syncthreads();                 // previous compute done — safe to overwrite
        As[a_k + 0][a_m] = av.x;
        As[a_k + 1][a_m] = av.y;
        As[a_k + 2][a_m] = av.z;
        As[a_k + 3][a_m] = av.w;
        *(float4*)&Ws[w_k][w_n]     = wv0;
        *(float4*)&Ws[w_k][w_n + 4] = wv1;
        __syncthreads();

        if (t + 1 < ntiles) {            // prefetch next tile (in flight during compute)
            int kn = kbeg + (t + 1) * 16;
            const float* Ap = (kn < K1len)
                ? (A1 + (size_t)a_m * H + (kn + a_k))
                : (A2 + (size_t)a_m * H + (kn - K1len + a_k));
            av  = *(const float4*)Ap;
            wv0 = *(const float4*)(W + (size_t)(kn + w_k) * H + n0 + w_n);
            wv1 = *(const float4*)(W + (size_t)(kn + w_k) * H + n0 + w_n + 4);
        }

        #pragma unroll
        for (int k = 0; k < 16; k++) {
            float4 a  = *(const float4*)&As[k][ty * 4];
            float4 b0 = *(const float4*)&Ws[k][tx * 8];
            float4 b1 = *(const float4*)&Ws[k][tx * 8 + 4];
            const float am[4] = {a.x, a.y, a.z, a.w};
            #pragma unroll
            for (int m = 0; m < 4; m++) {
                acc[m][0] += am[m] * b0.x; acc[m][1] += am[m] * b0.y;
                acc[m][2] += am[m] * b0.z; acc[m][3] += am[m] * b0.w;
                acc[m][4] += am[m] * b1.x; acc[m][5] += am[m] * b1.y;
                acc[m][6] += am[m] * b1.z; acc[m][7] += am[m] * b1.w;
            }
        }
    }

    #pragma unroll
    for (int m = 0; m < 4; m++) {
        int row = ty * 4 + m;
        *(float4*)(C + (size_t)row * H + n0 + tx * 8)     =
            make_float4(acc[m][0], acc[m][1], acc[m][2], acc[m][3]);
        *(float4*)(C + (size_t)row * H + n0 + tx * 8 + 4) =
            make_float4(acc[m][4], acc[m][5], acc[m][6], acc[m][7]);
    }
}

// Deterministic 8-way split-K reduction (+ optional tanh), float4-vectorized.
__global__ void reduce8_kernel(const float* __restrict__ in, float* __restrict__ outp, int do_tanh)
{
    int i = blockIdx.x * 256 + threadIdx.x;        // float4 index, 0..49151
    const int S = MAT / 4;
    if (i >= S) return;
    const float4* p = (const float4*)in;
    float4 v = p[i];
    #pragma unroll
    for (int j = 1; j < KSPLIT; j++) {
        float4 a = p[i + j * S];
        v.x += a.x; v.y += a.y; v.z += a.z; v.w += a.w;
    }
    if (do_tanh) { v.x = tanhf(v.x); v.y = tanhf(v.y); v.z = tanhf(v.z); v.w = tanhf(v.w); }
    ((float4*)outp)[i] = v;
}

// Deterministic 4-way reduction (wctx partials).
__global__ void reduce4_kernel(const float* __restrict__ in, float* __restrict__ outp)
{
    int i = blockIdx.x * 256 + threadIdx.x;
    const int S = MAT / 4;
    if (i >= S) return;
    const float4* p = (const float4*)in;
    float4 a = p[i], b = p[i + S], c = p[i + 2 * S], d = p[i + 3 * S];
    float4 v;
    v.x = a.x + b.x + c.x + d.x;
    v.y = a.y + b.y + c.y + d.y;
    v.z = a.z + b.z + c.z + d.z;
    v.w = a.w + b.w + c.w + d.w;
    ((float4*)outp)[i] = v;
}

// scores[rel][b][l] = dot(enc[b,l,:], target[rel][b,:]). One block per
// (64-l chunk, b); each warp handles 8 l-rows. Targets staged once per block.
// grid = (8, 64), block = 256.
__global__ __launch_bounds__(256) void scores_kernel(
    const float* __restrict__ enc, const float* __restrict__ target, float* __restrict__ scores)
{
    const int b    = blockIdx.y;
    const int warp = threadIdx.x >> 5;
    const int lane = threadIdx.x & 31;

    __shared__ __align__(16) float st[3][H];
    for (int i = threadIdx.x; i < 3 * H; i += 256)
        st[i >> 10][i & 1023] = target[(size_t)((i >> 10) * B + b) * H + (i & 1023)];
    __syncthreads();

    for (int li = 0; li < 8; li++) {
        const int l = blockIdx.x * 64 + li * 8 + warp;
        const float4* erow = (const float4*)(enc + ((size_t)b * L + l) * H);
        float s0 = 0.f, s1 = 0.f, s2 = 0.f;
        #pragma unroll
        for (int i = 0; i < 8; i++) {
            int h4 = lane + i * 32;
            float4 e  = erow[h4];
            float4 t0 = *(const float4*)&st[0][h4 * 4];
            float4 t1 = *(const float4*)&st[1][h4 * 4];
            float4 t2 = *(const float4*)&st[2][h4 * 4];
            s0 += e.x * t0.x + e.y * t0.y + e.z * t0.z + e.w * t0.w;
            s1 += e.x * t1.x + e.y * t1.y + e.z * t1.z + e.w * t1.w;
            s2 += e.x * t2.x + e.y * t2.y + e.z * t2.z + e.w * t2.w;
        }
        #pragma unroll
        for (int o = 16; o > 0; o >>= 1) {
            s0 += __shfl_down_sync(0xffffffffu, s0, o);
            s1 += __shfl_down_sync(0xffffffffu, s1, o);
            s2 += __shfl_down_sync(0xffffffffu, s2, o);
        }
        if (lane == 0) {
            scores[(size_t)(0 * B + b) * L + l] = s0;
            scores[(size_t)(1 * B + b) * L + l] = s1;
            scores[(size_t)(2 * B + b) * L + l] = s2;
        }
    }
}

// Fused softmax + weighted context. Each block recomputes the (cheap) full-row
// softmax from raw scores in smem, then accumulates its 128-l slice of
// wpart[ls][rel][b][h]. grid = (4 l-splits, 64 b), block = 256.
__global__ __launch_bounds__(256) void wctx_kernel(
    const float* __restrict__ enc, const float* __restrict__ scores, float* __restrict__ wpart)
{
    const int ls   = blockIdx.x;
    const int b    = blockIdx.y;
    const int t    = threadIdx.x;
    const int warp = t >> 5;
    const int lane = t & 31;

    __shared__ __align__(16) float sc[3][L];   // 6 KB raw scores -> probs

    for (int i = t; i < 3 * L; i += 256)
        sc[i >> 9][i & 511] = scores[(size_t)((i >> 9) * B + b) * L + (i & 511)];
    __syncthreads();

    if (warp < 3) {   // softmax over full L per rel (identical across the 4 ls-blocks)
        float* p = sc[warp];
        float v[16];
        float mx = -1e30f;
        #pragma unroll
        for (int i = 0; i < 16; i++) { v[i] = p[lane + i * 32]; mx = fmaxf(mx, v[i]); }
        #pragma unroll
        for (int o = 16; o > 0; o >>= 1) mx = fmaxf(mx, __shfl_xor_sync(0xffffffffu, mx, o));
        float sum = 0.f;
        #pragma unroll
        for (int i = 0; i < 16; i++) { v[i] = __expf(v[i] - mx); sum += v[i]; }
        #pragma unroll
        for (int o = 16; o > 0; o >>= 1) sum += __shfl_xor_sync(0xffffffffu, sum, o);
        float inv = 1.f / sum;
        #pragma unroll
        for (int i = 0; i < 16; i++) p[lane + i * 32] = v[i] * inv;
    }
    __syncthreads();

    const float4* e = (const float4*)(enc + ((size_t)b * L + ls * 128) * H) + t;
    float4 a0 = {0,0,0,0}, a1 = {0,0,0,0}, a2 = {0,0,0,0};
    #pragma unroll 4
    for (int l = 0; l < 128; l++) {
        float4 ev = e[(size_t)l * 256];
        float p0 = sc[0][ls * 128 + l], p1 = sc[1][ls * 128 + l], p2 = sc[2][ls * 128 + l];
        a0.x += p0 * ev.x; a0.y += p0 * ev.y; a0.z += p0 * ev.z; a0.w += p0 * ev.w;
        a1.x += p1 * ev.x; a1.y += p1 * ev.y; a1.z += p1 * ev.z; a1.w += p1 * ev.w;
        a2.x += p2 * ev.x; a2.y += p2 * ev.y; a2.z += p2 * ev.z; a2.w += p2 * ev.w;
    }
    float4* w = (float4*)(wpart + (size_t)ls * MAT);
    w[(size_t)(0 * B + b) * 256 + t] = a0;
    w[(size_t)(1 * B + b) * 256 + t] = a1;
    w[(size_t)(2 * B + b) * 256 + t] = a2;
}

// Sum final-GEMM split-K partials, tanh, broadcast F times to out[rel][b][f][h].
__global__ void bcast_kernel(const float* __restrict__ part, float* __restrict__ out, int F)
{
    int idx = blockIdx.x * 256 + threadIdx.x;      // 0..49151 float4 units
    const float4* p = (const float4*)part;
    const int S = MAT / 4;
    float4 v = p[idx];
    #pragma unroll
    for (int j = 1; j < KSPLIT; j++) {
        float4 a = p[idx + j * S];
        v.x += a.x; v.y += a.y; v.z += a.z; v.w += a.w;
    }
    v.x = tanhf(v.x); v.y = tanhf(v.y); v.z = tanhf(v.z); v.w = tanhf(v.w);
    int rb = idx >> 8;                             // rel*64 + b
    int h4 = idx & 255;
    float4* o = (float4*)out + (size_t)rb * F * 256 + h4;
    for (int f = 0; f < F; f++) o[(size_t)f * 256] = v;
}

// ---------------------------------------------------------------------------
extern "C" void kernel_launch(void* const* d_in, const int* in_sizes, int n_in,
                              void* d_out, int out_size)
{
    const float* h_s     = (const float*)d_in[0];
    const float* h_o     = (const float*)d_in[1];
    const float* h_a     = (const float*)d_in[2];
    const float* enc     = (const float*)d_in[3];
    // d_in[4] = full_feature_len (derived from out_size instead)
    const float* W_as    = (const float*)d_in[5];
    const float* W_so    = (const float*)d_in[6];
    const float* W_oa    = (const float*)d_in[7];
    const float* Win_as  = (const float*)d_in[8];
    const float* Win_so  = (const float*)d_in[9];
    const float* Win_oa  = (const float*)d_in[10];
    const float* Wout_as = (const float*)d_in[11];
    const float* Wout_so = (const float*)d_in[12];
    const float* Wout_oa = (const float*)d_in[13];
    float* out = (float*)d_out;
    const int F = out_size / (NREL * B * H);       // 36

    float *p_part, *p_hrel, *p_target, *p_scores, *p_wpart, *p_wctx;
    cudaGetSymbolAddress((void**)&p_part,   g_part);
    cudaGetSymbolAddress((void**)&p_hrel,   g_hrel);
    cudaGetSymbolAddress((void**)&p_target, g_target);
    cudaGetSymbolAddress((void**)&p_scores, g_scores);
    cudaGetSymbolAddress((void**)&p_wpart,  g_wpart);
    cudaGetSymbolAddress((void**)&p_wctx,   g_wctx);

    const dim3 gg(8, KSPLIT, 3);                   // 192 blocks

    // 1) h_rel = tanh(concat(h1,h2) @ W_rel)   [as: (a,s), so: (s,o), oa: (o,a)]
    gemm_concat_kernel<<<gg, 256>>>(h_a, h_s, h_o,   h_s, h_o, h_a,
                                    W_as, W_so, W_oa, p_part, H, 2 * H / KSPLIT);
    reduce8_kernel<<<192, 256>>>(p_part, p_hrel, 1);

    // 2) target = h_rel @ Win_rel
    gemm_concat_kernel<<<gg, 256>>>(p_hrel, p_hrel + B * H, p_hrel + 2 * B * H,
                                    p_hrel, p_hrel, p_hrel,   // unused (K2 side never hit)
                                    Win_as, Win_so, Win_oa, p_part, H, H / KSPLIT);
    reduce8_kernel<<<192, 256>>>(p_part, p_target, 0);

    // 3) raw scores ; fused softmax + weighted ctx ; reduce l-splits
    scores_kernel<<<dim3(8, 64), 256>>>(enc, p_target, p_scores);
    wctx_kernel<<<dim3(4, 64), 256>>>(enc, p_scores, p_wpart);
    reduce4_kernel<<<192, 256>>>(p_wpart, p_wctx);

    // 4) h_final = tanh(concat(wctx, h_rel) @ Wout_rel), broadcast to out
    gemm_concat_kernel<<<gg, 256>>>(p_wctx, p_wctx + B * H, p_wctx + 2 * B * H,
                                    p_hrel, p_hrel + B * H, p_hrel + 2 * B * H,
                                    Wout_as, Wout_so, Wout_oa, p_part, H, 2 * H / KSPLIT);
    bcast_kernel<<<192, 256>>>(p_part, out, F);
}

// round 8
// speedup vs baseline: 1.7085x; 1.5557x over previous
#include <cuda_runtime.h>
#include <cuda_bf16.h>
#include <mma.h>
#include <math.h>
#include <stdint.h>

using namespace nvcuda;

#define B 64
#define L 512
#define H 1024
#define NREL 3
#define KSPLIT 8
#define MAT (NREL * B * H)      // 196608 floats per [3][64][1024] matrix

// Scratch (device globals — no allocation allowed)
__device__ float g_part[KSPLIT * MAT];    // split-K GEMM partials (reused 3x)
__device__ float g_hrel[MAT];             // tanh(concat @ W_rel)
__device__ float g_target[MAT];           // h_rel @ Win
__device__ float g_scores[NREL * B * L];  // raw scores
__device__ float g_wpart[KSPLIT * MAT];   // weighted-ctx L-split partials
__device__ float g_wctx[MAT];             // weighted context

// fp32 -> bf16 hi/lo split
__device__ __forceinline__ void bsplit(float f, __nv_bfloat16& hi, __nv_bfloat16& lo) {
    hi = __float2bfloat16(f);
    lo = __float2bfloat16(f - __bfloat162float(hi));
}

// ---------------------------------------------------------------------------
// Tensor-core (mma.sync/WMMA) split-K GEMM over A = concat(A1[64,1024],
// A2[64,1024]) (row-major, stride 1024), W row-major [(K1+K2), 1024].
// bf16 2-term split: D = Ah*Wh + Ah*Wl + Al*Wh, fp32 accumulate.
// Plain (non-atomic) partials: Cpart[split][rel][64][1024].
// BM=64, BN=64, BK=16; 8 warps in 4(m) x 2(n) grid, each warp 16x32.
// grid = (16 n-tiles, KSPLIT, 3 rels), block = 256.
// ---------------------------------------------------------------------------
__global__ __launch_bounds__(256) void gemm_wmma_kernel(
    const float* __restrict__ A1_0, const float* __restrict__ A1_1, const float* __restrict__ A1_2,
    const float* __restrict__ A2_0, const float* __restrict__ A2_1, const float* __restrict__ A2_2,
    const float* __restrict__ W0,  const float* __restrict__ W1,  const float* __restrict__ W2,
    float* __restrict__ Cpart, int K1len, int kchunk)
{
    const int rel = blockIdx.z;
    const float* A1 = (rel == 0) ? A1_0 : (rel == 1) ? A1_1 : A1_2;
    const float* A2 = (rel == 0) ? A2_0 : (rel == 1) ? A2_1 : A2_2;
    const float* W  = (rel == 0) ? W0  : (rel == 1) ? W1  : W2;
    float* C = Cpart + (size_t)blockIdx.y * MAT + (size_t)rel * (B * H);

    const int n0     = blockIdx.x * 64;
    const int kbeg   = blockIdx.y * kchunk;
    const int ntiles = kchunk / 16;

    // Padded ld (multiple of 8 bf16 = 16B, conflict-stagger)
    __shared__ __align__(16) __nv_bfloat16 Ah[64][24], Al[64][24];   // 6 KB
    __shared__ __align__(16) __nv_bfloat16 Wh[16][72], Wl[16][72];   // 4.5 KB

    const int tid  = threadIdx.x;
    const int warp = tid >> 5;
    const int wm   = warp >> 1;          // 0..3 : m-tile (16 rows)
    const int wn   = warp & 1;           // 0..1 : n-tile (32 cols)

    const int a_m = tid >> 2;            // 0..63
    const int a_k = (tid & 3) * 4;       // 0,4,8,12
    const int w_k = tid >> 4;            // 0..15
    const int w_n = (tid & 15) * 4;      // 0..60

    wmma::fragment<wmma::accumulator, 16, 16, 16, float> acc[2];
    wmma::fill_fragment(acc[0], 0.0f);
    wmma::fill_fragment(acc[1], 0.0f);

    // Prologue: load k-tile 0 (BK=16 tiles never straddle the concat boundary)
    int k0 = kbeg;
    const float* Aptr = (k0 < K1len)
        ? (A1 + (size_t)a_m * H + (k0 + a_k))
        : (A2 + (size_t)a_m * H + (k0 - K1len + a_k));
    float4 av = *(const float4*)Aptr;
    float4 wv = *(const float4*)(W + (size_t)(k0 + w_k) * H + n0 + w_n);

    for (int t = 0; t < ntiles; t++) {
        __syncthreads();                 // previous compute done — safe to overwrite
        {
            __nv_bfloat16 h, l;
            bsplit(av.x, h, l); Ah[a_m][a_k + 0] = h; Al[a_m][a_k + 0] = l;
            bsplit(av.y, h, l); Ah[a_m][a_k + 1] = h; Al[a_m][a_k + 1] = l;
            bsplit(av.z, h, l); Ah[a_m][a_k + 2] = h; Al[a_m][a_k + 2] = l;
            bsplit(av.w, h, l); Ah[a_m][a_k + 3] = h; Al[a_m][a_k + 3] = l;
            bsplit(wv.x, h, l); Wh[w_k][w_n + 0] = h; Wl[w_k][w_n + 0] = l;
            bsplit(wv.y, h, l); Wh[w_k][w_n + 1] = h; Wl[w_k][w_n + 1] = l;
            bsplit(wv.z, h, l); Wh[w_k][w_n + 2] = h; Wl[w_k][w_n + 2] = l;
            bsplit(wv.w, h, l); Wh[w_k][w_n + 3] = h; Wl[w_k][w_n + 3] = l;
        }
        __syncthreads();

        if (t + 1 < ntiles) {            // register prefetch of next k-tile
            int kn = kbeg + (t + 1) * 16;
            const float* Ap = (kn < K1len)
                ? (A1 + (size_t)a_m * H + (kn + a_k))
                : (A2 + (size_t)a_m * H + (kn - K1len + a_k));
            av = *(const float4*)Ap;
            wv = *(const float4*)(W + (size_t)(kn + w_k) * H + n0 + w_n);
        }

        wmma::fragment<wmma::matrix_a, 16, 16, 16, __nv_bfloat16, wmma::row_major> aH, aL;
        wmma::load_matrix_sync(aH, &Ah[wm * 16][0], 24);
        wmma::load_matrix_sync(aL, &Al[wm * 16][0], 24);
        #pragma unroll
        for (int j = 0; j < 2; j++) {
            wmma::fragment<wmma::matrix_b, 16, 16, 16, __nv_bfloat16, wmma::row_major> bH, bL;
            wmma::load_matrix_sync(bH, &Wh[0][wn * 32 + j * 16], 72);
            wmma::load_matrix_sync(bL, &Wl[0][wn * 32 + j * 16], 72);
            wmma::mma_sync(acc[j], aH, bH, acc[j]);
            wmma::mma_sync(acc[j], aH, bL, acc[j]);
            wmma::mma_sync(acc[j], aL, bH, acc[j]);
        }
    }

    #pragma unroll
    for (int j = 0; j < 2; j++)
        wmma::store_matrix_sync(C + (size_t)(wm * 16) * H + n0 + wn * 32 + j * 16,
                                acc[j], H, wmma::mem_row_major);
}

// Deterministic 8-way split reduction (+ optional tanh), float4-vectorized.
__global__ void reduce8_kernel(const float* __restrict__ in, float* __restrict__ outp, int do_tanh)
{
    int i = blockIdx.x * 256 + threadIdx.x;        // float4 index, 0..49151
    const int S = MAT / 4;
    if (i >= S) return;
    const float4* p = (const float4*)in;
    float4 v = p[i];
    #pragma unroll
    for (int j = 1; j < KSPLIT; j++) {
        float4 a = p[i + j * S];
        v.x += a.x; v.y += a.y; v.z += a.z; v.w += a.w;
    }
    if (do_tanh) { v.x = tanhf(v.x); v.y = tanhf(v.y); v.z = tanhf(v.z); v.w = tanhf(v.w); }
    ((float4*)outp)[i] = v;
}

// scores[rel][b][l] = dot(enc[b,l,:], target[rel][b,:]). One block per
// (64-l chunk, b); each warp handles 8 l-rows. grid = (8, 64), block = 256.
__global__ __launch_bounds__(256) void scores_kernel(
    const float* __restrict__ enc, const float* __restrict__ target, float* __restrict__ scores)
{
    const int b    = blockIdx.y;
    const int warp = threadIdx.x >> 5;
    const int lane = threadIdx.x & 31;

    __shared__ __align__(16) float st[3][H];
    for (int i = threadIdx.x; i < 3 * H; i += 256)
        st[i >> 10][i & 1023] = target[(size_t)((i >> 10) * B + b) * H + (i & 1023)];
    __syncthreads();

    for (int li = 0; li < 8; li++) {
        const int l = blockIdx.x * 64 + li * 8 + warp;
        const float4* erow = (const float4*)(enc + ((size_t)b * L + l) * H);
        float s0 = 0.f, s1 = 0.f, s2 = 0.f;
        #pragma unroll
        for (int i = 0; i < 8; i++) {
            int h4 = lane + i * 32;
            float4 e  = erow[h4];
            float4 t0 = *(const float4*)&st[0][h4 * 4];
            float4 t1 = *(const float4*)&st[1][h4 * 4];
            float4 t2 = *(const float4*)&st[2][h4 * 4];
            s0 += e.x * t0.x + e.y * t0.y + e.z * t0.z + e.w * t0.w;
            s1 += e.x * t1.x + e.y * t1.y + e.z * t1.z + e.w * t1.w;
            s2 += e.x * t2.x + e.y * t2.y + e.z * t2.z + e.w * t2.w;
        }
        #pragma unroll
        for (int o = 16; o > 0; o >>= 1) {
            s0 += __shfl_down_sync(0xffffffffu, s0, o);
            s1 += __shfl_down_sync(0xffffffffu, s1, o);
            s2 += __shfl_down_sync(0xffffffffu, s2, o);
        }
        if (lane == 0) {
            scores[(size_t)(0 * B + b) * L + l] = s0;
            scores[(size_t)(1 * B + b) * L + l] = s1;
            scores[(size_t)(2 * B + b) * L + l] = s2;
        }
    }
}

// Fused softmax + weighted context. Each block recomputes full-row softmax
// from raw scores, then accumulates a 64-l slice of wpart[ls][rel][b][h].
// grid = (8 l-splits, 64 b), block = 256.
__global__ __launch_bounds__(256) void wctx_kernel(
    const float* __restrict__ enc, const float* __restrict__ scores, float* __restrict__ wpart)
{
    const int ls   = blockIdx.x;
    const int b    = blockIdx.y;
    const int t    = threadIdx.x;
    const int warp = t >> 5;
    const int lane = t & 31;

    __shared__ __align__(16) float sc[3][L];   // raw scores -> probs

    for (int i = t; i < 3 * L; i += 256)
        sc[i >> 9][i & 511] = scores[(size_t)((i >> 9) * B + b) * L + (i & 511)];
    __syncthreads();

    if (warp < 3) {   // softmax over full L per rel (identical across ls-blocks)
        float* p = sc[warp];
        float v[16];
        float mx = -1e30f;
        #pragma unroll
        for (int i = 0; i < 16; i++) { v[i] = p[lane + i * 32]; mx = fmaxf(mx, v[i]); }
        #pragma unroll
        for (int o = 16; o > 0; o >>= 1) mx = fmaxf(mx, __shfl_xor_sync(0xffffffffu, mx, o));
        float sum = 0.f;
        #pragma unroll
        for (int i = 0; i < 16; i++) { v[i] = __expf(v[i] - mx); sum += v[i]; }
        #pragma unroll
        for (int o = 16; o > 0; o >>= 1) sum += __shfl_xor_sync(0xffffffffu, sum, o);
        float inv = 1.f / sum;
        #pragma unroll
        for (int i = 0; i < 16; i++) p[lane + i * 32] = v[i] * inv;
    }
    __syncthreads();

    const float4* e = (const float4*)(enc + ((size_t)b * L + ls * 64) * H) + t;
    float4 a0 = {0,0,0,0}, a1 = {0,0,0,0}, a2 = {0,0,0,0};
    #pragma unroll 4
    for (int l = 0; l < 64; l++) {
        float4 ev = e[(size_t)l * 256];
        float p0 = sc[0][ls * 64 + l], p1 = sc[1][ls * 64 + l], p2 = sc[2][ls * 64 + l];
        a0.x += p0 * ev.x; a0.y += p0 * ev.y; a0.z += p0 * ev.z; a0.w += p0 * ev.w;
        a1.x += p1 * ev.x; a1.y += p1 * ev.y; a1.z += p1 * ev.z; a1.w += p1 * ev.w;
        a2.x += p2 * ev.x; a2.y += p2 * ev.y; a2.z += p2 * ev.z; a2.w += p2 * ev.w;
    }
    float4* w = (float4*)(wpart + (size_t)ls * MAT);
    w[(size_t)(0 * B + b) * 256 + t] = a0;
    w[(size_t)(1 * B + b) * 256 + t] = a1;
    w[(size_t)(2 * B + b) * 256 + t] = a2;
}

// Sum final-GEMM split-K partials, tanh, broadcast F times to out[rel][b][f][h].
__global__ void bcast_kernel(const float* __restrict__ part, float* __restrict__ out, int F)
{
    int idx = blockIdx.x * 256 + threadIdx.x;      // 0..49151 float4 units
    const float4* p = (const float4*)part;
    const int S = MAT / 4;
    float4 v = p[idx];
    #pragma unroll
    for (int j = 1; j < KSPLIT; j++) {
        float4 a = p[idx + j * S];
        v.x += a.x; v.y += a.y; v.z += a.z; v.w += a.w;
    }
    v.x = tanhf(v.x); v.y = tanhf(v.y); v.z = tanhf(v.z); v.w = tanhf(v.w);
    int rb = idx >> 8;                             // rel*64 + b
    int h4 = idx & 255;
    float4* o = (float4*)out + (size_t)rb * F * 256 + h4;
    for (int f = 0; f < F; f++) o[(size_t)f * 256] = v;
}

// ---------------------------------------------------------------------------
extern "C" void kernel_launch(void* const* d_in, const int* in_sizes, int n_in,
                              void* d_out, int out_size)
{
    const float* h_s     = (const float*)d_in[0];
    const float* h_o     = (const float*)d_in[1];
    const float* h_a     = (const float*)d_in[2];
    const float* enc     = (const float*)d_in[3];
    // d_in[4] = full_feature_len (derived from out_size instead)
    const float* W_as    = (const float*)d_in[5];
    const float* W_so    = (const float*)d_in[6];
    const float* W_oa    = (const float*)d_in[7];
    const float* Win_as  = (const float*)d_in[8];
    const float* Win_so  = (const float*)d_in[9];
    const float* Win_oa  = (const float*)d_in[10];
    const float* Wout_as = (const float*)d_in[11];
    const float* Wout_so = (const float*)d_in[12];
    const float* Wout_oa = (const float*)d_in[13];
    float* out = (float*)d_out;
    const int F = out_size / (NREL * B * H);       // 36

    float *p_part, *p_hrel, *p_target, *p_scores, *p_wpart, *p_wctx;
    cudaGetSymbolAddress((void**)&p_part,   g_part);
    cudaGetSymbolAddress((void**)&p_hrel,   g_hrel);
    cudaGetSymbolAddress((void**)&p_target, g_target);
    cudaGetSymbolAddress((void**)&p_scores, g_scores);
    cudaGetSymbolAddress((void**)&p_wpart,  g_wpart);
    cudaGetSymbolAddress((void**)&p_wctx,   g_wctx);

    const dim3 gg(16, KSPLIT, 3);                  // 384 blocks

    // 1) h_rel = tanh(concat(h1,h2) @ W_rel)   [as: (a,s), so: (s,o), oa: (o,a)]
    gemm_wmma_kernel<<<gg, 256>>>(h_a, h_s, h_o,   h_s, h_o, h_a,
                                  W_as, W_so, W_oa, p_part, H, 2 * H / KSPLIT);
    reduce8_kernel<<<192, 256>>>(p_part, p_hrel, 1);

    // 2) target = h_rel @ Win_rel
    gemm_wmma_kernel<<<gg, 256>>>(p_hrel, p_hrel + B * H, p_hrel + 2 * B * H,
                                  p_hrel, p_hrel, p_hrel,   // unused (K1len = 2H)
                                  Win_as, Win_so, Win_oa, p_part, 2 * H, H / KSPLIT);
    reduce8_kernel<<<192, 256>>>(p_part, p_target, 0);

    // 3) raw scores ; fused softmax + weighted ctx ; reduce l-splits
    scores_kernel<<<dim3(8, 64), 256>>>(enc, p_target, p_scores);
    wctx_kernel<<<dim3(8, 64), 256>>>(enc, p_scores, p_wpart);
    reduce8_kernel<<<192, 256>>>(p_wpart, p_wctx, 0);

    // 4) h_final = tanh(concat(wctx, h_rel) @ Wout_rel), broadcast to out
    gemm_wmma_kernel<<<gg, 256>>>(p_wctx, p_wctx + B * H, p_wctx + 2 * B * H,
                                  p_hrel, p_hrel + B * H, p_hrel + 2 * B * H,
                                  Wout_as, Wout_so, Wout_oa, p_part, H, 2 * H / KSPLIT);
    bcast_kernel<<<192, 256>>>(p_part, out, F);
}

// round 9
// speedup vs baseline: 1.9614x; 1.1481x over previous
#include <cuda_runtime.h>
#include <cuda_bf16.h>
#include <mma.h>
#include <math.h>
#include <stdint.h>

using namespace nvcuda;

#define B 64
#define L 512
#define H 1024
#define NREL 3
#define KSPLIT 8
#define LSPLIT 8
#define MAT (NREL * B * H)      // 196608 floats per [3][64][1024] matrix

// Scratch (device globals — no allocation allowed)
__device__ float g_part[KSPLIT * MAT];    // split-K GEMM partials (reused 3x)
__device__ float g_hrel[MAT];             // tanh(concat @ W_rel)
__device__ float g_target[MAT];           // h_rel @ Win
__device__ float g_wpart[LSPLIT * MAT];   // weighted-ctx l-split partials (unnormalized)
__device__ float g_mstat[LSPLIT * NREL * B];  // per-split running max
__device__ float g_sstat[LSPLIT * NREL * B];  // per-split running sum
__device__ float g_wctx[MAT];             // weighted context

// fp32 -> bf16 hi/lo split
__device__ __forceinline__ void bsplit(float f, __nv_bfloat16& hi, __nv_bfloat16& lo) {
    hi = __float2bfloat16(f);
    lo = __float2bfloat16(f - __bfloat162float(hi));
}

// ---------------------------------------------------------------------------
// Tensor-core (mma.sync/WMMA) split-K GEMM over A = concat(A1[64,1024],
// A2[64,1024]) (row-major, stride 1024), W row-major [(K1+K2), 1024].
// bf16 2-term split: D = Ah*Wh + Ah*Wl + Al*Wh, fp32 accumulate.
// Plain (non-atomic) partials: Cpart[split][rel][64][1024].
// BM=64, BN=64, BK=16; 8 warps in 4(m) x 2(n) grid, each warp 16x32.
// grid = (16 n-tiles, KSPLIT, 3 rels), block = 256.
// ---------------------------------------------------------------------------
__global__ __launch_bounds__(256) void gemm_wmma_kernel(
    const float* __restrict__ A1_0, const float* __restrict__ A1_1, const float* __restrict__ A1_2,
    const float* __restrict__ A2_0, const float* __restrict__ A2_1, const float* __restrict__ A2_2,
    const float* __restrict__ W0,  const float* __restrict__ W1,  const float* __restrict__ W2,
    float* __restrict__ Cpart, int K1len, int kchunk)
{
    const int rel = blockIdx.z;
    const float* A1 = (rel == 0) ? A1_0 : (rel == 1) ? A1_1 : A1_2;
    const float* A2 = (rel == 0) ? A2_0 : (rel == 1) ? A2_1 : A2_2;
    const float* W  = (rel == 0) ? W0  : (rel == 1) ? W1  : W2;
    float* C = Cpart + (size_t)blockIdx.y * MAT + (size_t)rel * (B * H);

    const int n0     = blockIdx.x * 64;
    const int kbeg   = blockIdx.y * kchunk;
    const int ntiles = kchunk / 16;

    // Padded ld (multiple of 8 bf16 = 16B, conflict-stagger)
    __shared__ __align__(16) __nv_bfloat16 Ah[64][24], Al[64][24];   // 6 KB
    __shared__ __align__(16) __nv_bfloat16 Wh[16][72], Wl[16][72];   // 4.5 KB

    const int tid  = threadIdx.x;
    const int warp = tid >> 5;
    const int wm   = warp >> 1;          // 0..3 : m-tile (16 rows)
    const int wn   = warp & 1;           // 0..1 : n-tile (32 cols)

    const int a_m = tid >> 2;            // 0..63
    const int a_k = (tid & 3) * 4;       // 0,4,8,12
    const int w_k = tid >> 4;            // 0..15
    const int w_n = (tid & 15) * 4;      // 0..60

    wmma::fragment<wmma::accumulator, 16, 16, 16, float> acc[2];
    wmma::fill_fragment(acc[0], 0.0f);
    wmma::fill_fragment(acc[1], 0.0f);

    // Prologue: load k-tile 0 (BK=16 tiles never straddle the concat boundary)
    int k0 = kbeg;
    const float* Aptr = (k0 < K1len)
        ? (A1 + (size_t)a_m * H + (k0 + a_k))
        : (A2 + (size_t)a_m * H + (k0 - K1len + a_k));
    float4 av = *(const float4*)Aptr;
    float4 wv = *(const float4*)(W + (size_t)(k0 + w_k) * H + n0 + w_n);

    for (int t = 0; t < ntiles; t++) {
        __syncthreads();                 // previous compute done — safe to overwrite
        {
            __nv_bfloat16 h, l;
            bsplit(av.x, h, l); Ah[a_m][a_k + 0] = h; Al[a_m][a_k + 0] = l;
            bsplit(av.y, h, l); Ah[a_m][a_k + 1] = h; Al[a_m][a_k + 1] = l;
            bsplit(av.z, h, l); Ah[a_m][a_k + 2] = h; Al[a_m][a_k + 2] = l;
            bsplit(av.w, h, l); Ah[a_m][a_k + 3] = h; Al[a_m][a_k + 3] = l;
            bsplit(wv.x, h, l); Wh[w_k][w_n + 0] = h; Wl[w_k][w_n + 0] = l;
            bsplit(wv.y, h, l); Wh[w_k][w_n + 1] = h; Wl[w_k][w_n + 1] = l;
            bsplit(wv.z, h, l); Wh[w_k][w_n + 2] = h; Wl[w_k][w_n + 2] = l;
            bsplit(wv.w, h, l); Wh[w_k][w_n + 3] = h; Wl[w_k][w_n + 3] = l;
        }
        __syncthreads();

        if (t + 1 < ntiles) {            // register prefetch of next k-tile
            int kn = kbeg + (t + 1) * 16;
            const float* Ap = (kn < K1len)
                ? (A1 + (size_t)a_m * H + (kn + a_k))
                : (A2 + (size_t)a_m * H + (kn - K1len + a_k));
            av = *(const float4*)Ap;
            wv = *(const float4*)(W + (size_t)(kn + w_k) * H + n0 + w_n);
        }

        wmma::fragment<wmma::matrix_a, 16, 16, 16, __nv_bfloat16, wmma::row_major> aH, aL;
        wmma::load_matrix_sync(aH, &Ah[wm * 16][0], 24);
        wmma::load_matrix_sync(aL, &Al[wm * 16][0], 24);
        #pragma unroll
        for (int j = 0; j < 2; j++) {
            wmma::fragment<wmma::matrix_b, 16, 16, 16, __nv_bfloat16, wmma::row_major> bH, bL;
            wmma::load_matrix_sync(bH, &Wh[0][wn * 32 + j * 16], 72);
            wmma::load_matrix_sync(bL, &Wl[0][wn * 32 + j * 16], 72);
            wmma::mma_sync(acc[j], aH, bH, acc[j]);
            wmma::mma_sync(acc[j], aH, bL, acc[j]);
            wmma::mma_sync(acc[j], aL, bH, acc[j]);
        }
    }

    #pragma unroll
    for (int j = 0; j < 2; j++)
        wmma::store_matrix_sync(C + (size_t)(wm * 16) * H + n0 + wn * 32 + j * 16,
                                acc[j], H, wmma::mem_row_major);
}

// Deterministic 8-way split reduction (+ optional tanh), float4-vectorized.
__global__ void reduce8_kernel(const float* __restrict__ in, float* __restrict__ outp, int do_tanh)
{
    int i = blockIdx.x * 256 + threadIdx.x;        // float4 index, 0..49151
    const int S = MAT / 4;
    if (i >= S) return;
    const float4* p = (const float4*)in;
    float4 v = p[i];
    #pragma unroll
    for (int j = 1; j < KSPLIT; j++) {
        float4 a = p[i + j * S];
        v.x += a.x; v.y += a.y; v.z += a.z; v.w += a.w;
    }
    if (do_tanh) { v.x = tanhf(v.x); v.y = tanhf(v.y); v.z = tanhf(v.z); v.w = tanhf(v.w); }
    ((float4*)outp)[i] = v;
}

// ---------------------------------------------------------------------------
// Flash-style single-pass attention with split-L online softmax.
// Each block = (ls, b) handles 64 enc rows in 8 chunks of 8:
//   chunk: load 8 rows into smem + compute 3 score dots on the fly,
//          online-softmax update (running max/sum + rescale),
//          accumulate unnormalized weighted context from the smem rows.
// enc is read from DRAM exactly once. Writes wpart[ls][rel][b][h] plus
// per-split (m, s) stats; combine_kernel merges splits exactly.
// grid = (LSPLIT, 64 b), block = 256.
// ---------------------------------------------------------------------------
__global__ __launch_bounds__(256) void attn_kernel(
    const float* __restrict__ enc, const float* __restrict__ target,
    float* __restrict__ wpart, float* __restrict__ mstat, float* __restrict__ sstat)
{
    const int ls   = blockIdx.x;
    const int b    = blockIdx.y;
    const int tid  = threadIdx.x;
    const int warp = tid >> 5;
    const int lane = tid & 31;

    __shared__ __align__(16) float st[3][H];      // 12 KB targets
    __shared__ __align__(16) float4 buf[8][256];  // 32 KB row chunk
    __shared__ float sch[3][8];                   // chunk scores
    __shared__ float s_p[3][8];                   // chunk unnormalized probs
    __shared__ float s_f[3];                      // rescale factor this chunk
    __shared__ float s_m[3], s_s[3];              // running max / sum

    for (int i = tid; i < 3 * H; i += 256)
        st[i >> 10][i & 1023] = target[(size_t)((i >> 10) * B + b) * H + (i & 1023)];
    if (tid < 3) { s_m[tid] = -1e30f; s_s[tid] = 0.f; }
    __syncthreads();

    float4 a0 = {0,0,0,0}, a1 = {0,0,0,0}, a2 = {0,0,0,0};

    for (int c = 0; c < 8; c++) {
        // Load 8 rows (warp w -> row w) into smem, computing score dots on the fly
        {
            const int l = ls * 64 + c * 8 + warp;
            const float4* erow = (const float4*)(enc + ((size_t)b * L + l) * H);
            float d0 = 0.f, d1 = 0.f, d2 = 0.f;
            #pragma unroll
            for (int i = 0; i < 8; i++) {
                int h4 = lane + i * 32;
                float4 e = erow[h4];
                buf[warp][h4] = e;
                float4 t0 = *(const float4*)&st[0][h4 * 4];
                float4 t1 = *(const float4*)&st[1][h4 * 4];
                float4 t2 = *(const float4*)&st[2][h4 * 4];
                d0 += e.x * t0.x + e.y * t0.y + e.z * t0.z + e.w * t0.w;
                d1 += e.x * t1.x + e.y * t1.y + e.z * t1.z + e.w * t1.w;
                d2 += e.x * t2.x + e.y * t2.y + e.z * t2.z + e.w * t2.w;
            }
            #pragma unroll
            for (int o = 16; o > 0; o >>= 1) {
                d0 += __shfl_down_sync(0xffffffffu, d0, o);
                d1 += __shfl_down_sync(0xffffffffu, d1, o);
                d2 += __shfl_down_sync(0xffffffffu, d2, o);
            }
            if (lane == 0) { sch[0][warp] = d0; sch[1][warp] = d1; sch[2][warp] = d2; }
        }
        __syncthreads();

        // Online softmax update (threads 0..2, one per rel)
        if (tid < 3) {
            const int r = tid;
            float m_new = s_m[r];
            #pragma unroll
            for (int j = 0; j < 8; j++) m_new = fmaxf(m_new, sch[r][j]);
            float f = __expf(s_m[r] - m_new);     // exp(-inf - m) = 0 on first chunk
            float s = s_s[r] * f;
            #pragma unroll
            for (int j = 0; j < 8; j++) {
                float p = __expf(sch[r][j] - m_new);
                s_p[r][j] = p;
                s += p;
            }
            s_m[r] = m_new; s_s[r] = s; s_f[r] = f;
        }
        __syncthreads();

        // Rescale accumulators, then add this chunk's weighted rows
        {
            float f0 = s_f[0], f1 = s_f[1], f2 = s_f[2];
            a0.x *= f0; a0.y *= f0; a0.z *= f0; a0.w *= f0;
            a1.x *= f1; a1.y *= f1; a1.z *= f1; a1.w *= f1;
            a2.x *= f2; a2.y *= f2; a2.z *= f2; a2.w *= f2;
            #pragma unroll
            for (int l = 0; l < 8; l++) {
                float4 e = buf[l][tid];
                float p0 = s_p[0][l], p1 = s_p[1][l], p2 = s_p[2][l];
                a0.x += p0 * e.x; a0.y += p0 * e.y; a0.z += p0 * e.z; a0.w += p0 * e.w;
                a1.x += p1 * e.x; a1.y += p1 * e.y; a1.z += p1 * e.z; a1.w += p1 * e.w;
                a2.x += p2 * e.x; a2.y += p2 * e.y; a2.z += p2 * e.z; a2.w += p2 * e.w;
            }
        }
        __syncthreads();   // buf/sch reused next chunk
    }

    float4* w = (float4*)(wpart + (size_t)ls * MAT);
    w[(size_t)(0 * B + b) * 256 + tid] = a0;
    w[(size_t)(1 * B + b) * 256 + tid] = a1;
    w[(size_t)(2 * B + b) * 256 + tid] = a2;
    if (tid < 3) {
        mstat[ls * (NREL * B) + tid * B + b] = s_m[tid];
        sstat[ls * (NREL * B) + tid * B + b] = s_s[tid];
    }
}

// Merge l-split partials: exact softmax via per-split (m, s) stats.
// One block per (rel, b) = 192 blocks, 256 threads (one float4 h-col each).
__global__ __launch_bounds__(256) void combine_kernel(
    const float* __restrict__ wpart, const float* __restrict__ mstat,
    const float* __restrict__ sstat, float* __restrict__ wctx)
{
    const int rb  = blockIdx.x;          // rel*64 + b
    const int tid = threadIdx.x;
    __shared__ float wsc[LSPLIT];

    if (tid == 0) {
        float m[LSPLIT], M = -1e30f;
        #pragma unroll
        for (int j = 0; j < LSPLIT; j++) { m[j] = mstat[j * (NREL * B) + rb]; M = fmaxf(M, m[j]); }
        float T = 0.f, e[LSPLIT];
        #pragma unroll
        for (int j = 0; j < LSPLIT; j++) {
            e[j] = __expf(m[j] - M);
            T += sstat[j * (NREL * B) + rb] * e[j];
        }
        float inv = 1.f / T;
        #pragma unroll
        for (int j = 0; j < LSPLIT; j++) wsc[j] = e[j] * inv;
    }
    __syncthreads();

    const float4* p = (const float4*)wpart;
    float4 v = {0,0,0,0};
    #pragma unroll
    for (int j = 0; j < LSPLIT; j++) {
        float4 a = p[(size_t)j * (MAT / 4) + (size_t)rb * 256 + tid];
        float s = wsc[j];
        v.x += s * a.x; v.y += s * a.y; v.z += s * a.z; v.w += s * a.w;
    }
    ((float4*)wctx)[(size_t)rb * 256 + tid] = v;
}

// Sum final-GEMM split-K partials, tanh, broadcast F times to out[rel][b][f][h].
__global__ void bcast_kernel(const float* __restrict__ part, float* __restrict__ out, int F)
{
    int idx = blockIdx.x * 256 + threadIdx.x;      // 0..49151 float4 units
    const float4* p = (const float4*)part;
    const int S = MAT / 4;
    float4 v = p[idx];
    #pragma unroll
    for (int j = 1; j < KSPLIT; j++) {
        float4 a = p[idx + j * S];
        v.x += a.x; v.y += a.y; v.z += a.z; v.w += a.w;
    }
    v.x = tanhf(v.x); v.y = tanhf(v.y); v.z = tanhf(v.z); v.w = tanhf(v.w);
    int rb = idx >> 8;                             // rel*64 + b
    int h4 = idx & 255;
    float4* o = (float4*)out + (size_t)rb * F * 256 + h4;
    for (int f = 0; f < F; f++) o[(size_t)f * 256] = v;
}

// ---------------------------------------------------------------------------
extern "C" void kernel_launch(void* const* d_in, const int* in_sizes, int n_in,
                              void* d_out, int out_size)
{
    const float* h_s     = (const float*)d_in[0];
    const float* h_o     = (const float*)d_in[1];
    const float* h_a     = (const float*)d_in[2];
    const float* enc     = (const float*)d_in[3];
    // d_in[4] = full_feature_len (derived from out_size instead)
    const float* W_as    = (const float*)d_in[5];
    const float* W_so    = (const float*)d_in[6];
    const float* W_oa    = (const float*)d_in[7];
    const float* Win_as  = (const float*)d_in[8];
    const float* Win_so  = (const float*)d_in[9];
    const float* Win_oa  = (const float*)d_in[10];
    const float* Wout_as = (const float*)d_in[11];
    const float* Wout_so = (const float*)d_in[12];
    const float* Wout_oa = (const float*)d_in[13];
    float* out = (float*)d_out;
    const int F = out_size / (NREL * B * H);       // 36

    float *p_part, *p_hrel, *p_target, *p_wpart, *p_mstat, *p_sstat, *p_wctx;
    cudaGetSymbolAddress((void**)&p_part,   g_part);
    cudaGetSymbolAddress((void**)&p_hrel,   g_hrel);
    cudaGetSymbolAddress((void**)&p_target, g_target);
    cudaGetSymbolAddress((void**)&p_wpart,  g_wpart);
    cudaGetSymbolAddress((void**)&p_mstat,  g_mstat);
    cudaGetSymbolAddress((void**)&p_sstat,  g_sstat);
    cudaGetSymbolAddress((void**)&p_wctx,   g_wctx);

    const dim3 gg(16, KSPLIT, 3);                  // 384 blocks

    // 1) h_rel = tanh(concat(h1,h2) @ W_rel)   [as: (a,s), so: (s,o), oa: (o,a)]
    gemm_wmma_kernel<<<gg, 256>>>(h_a, h_s, h_o,   h_s, h_o, h_a,
                                  W_as, W_so, W_oa, p_part, H, 2 * H / KSPLIT);
    reduce8_kernel<<<192, 256>>>(p_part, p_hrel, 1);

    // 2) target = h_rel @ Win_rel
    gemm_wmma_kernel<<<gg, 256>>>(p_hrel, p_hrel + B * H, p_hrel + 2 * B * H,
                                  p_hrel, p_hrel, p_hrel,   // unused (K1len = 2H)
                                  Win_as, Win_so, Win_oa, p_part, 2 * H, H / KSPLIT);
    reduce8_kernel<<<192, 256>>>(p_part, p_target, 0);

    // 3) single-pass flash attention (scores+softmax+wctx), then split combine
    attn_kernel<<<dim3(LSPLIT, 64), 256>>>(enc, p_target, p_wpart, p_mstat, p_sstat);
    combine_kernel<<<192, 256>>>(p_wpart, p_mstat, p_sstat, p_wctx);

    // 4) h_final = tanh(concat(wctx, h_rel) @ Wout_rel), broadcast to out
    gemm_wmma_kernel<<<gg, 256>>>(p_wctx, p_wctx + B * H, p_wctx + 2 * B * H,
                                  p_hrel, p_hrel + B * H, p_hrel + 2 * B * H,
                                  Wout_as, Wout_so, Wout_oa, p_part, H, 2 * H / KSPLIT);
    bcast_kernel<<<192, 256>>>(p_part, out, F);
}